// round 1
// baseline (speedup 1.0000x reference)
#include <cuda_runtime.h>
#include <cstdint>

// Problem constants (fixed shapes from reference: B=8, N=8192, D=64, F=64)
#define TOTAL_POINTS 65536
#define CHUNK 4
#define NCHUNKS (TOTAL_POINTS / CHUNK)   // 16384
#define THREADS 256
#define GRID 1024                         // 16384/1024 = 16 chunks per block exactly

typedef unsigned long long ull;

__device__ __forceinline__ void fma2(ull &acc, ull a, ull b) {
    asm("fma.rn.f32x2 %0, %1, %2, %0;" : "+l"(acc) : "l"(a), "l"(b));
}
__device__ __forceinline__ ull add2(ull a, ull b) {
    ull r; asm("add.rn.f32x2 %0, %1, %2;" : "=l"(r) : "l"(a), "l"(b)); return r;
}
__device__ __forceinline__ ull dup2(float w) {
    ull r; asm("mov.b64 %0, {%1, %1};" : "=l"(r) : "r"(__float_as_uint(w))); return r;
}
__device__ __forceinline__ float lo32(ull v) { return __uint_as_float((unsigned)v); }
__device__ __forceinline__ float hi32(ull v) { return __uint_as_float((unsigned)(v >> 32)); }

__global__ void __launch_bounds__(THREADS, 2)
affine_linear_kernel(const float* __restrict__ X, const float* __restrict__ J,
                     const float* __restrict__ A, const float* __restrict__ Bm,
                     const float* __restrict__ C, float* __restrict__ Y)
{
    // T layout: [e(192)][i(3)][p(4)] floats, e-stride = 12 floats (48B)
    __shared__ float T_s[192 * 12];

    const int tid = threadIdx.x;
    const int f = tid >> 2;      // 0..63  (output row, phase B)
    const int g = tid & 3;       // 0..3   (e partition, phase B)
    const int p = tid >> 6;      // 0..3   (point within chunk, phase A)
    const int d = tid & 63;      // 0..63  (frame index, phase A)

    // W = [A | Bm | C] row f, columns e = 4j+g (j = 0..47), held in registers.
    float W_reg[48];
#pragma unroll
    for (int j = 0; j < 16; ++j) W_reg[j]      = A [f * 64 + 4 * j + g];
#pragma unroll
    for (int j = 0; j < 16; ++j) W_reg[16 + j] = Bm[f * 64 + 4 * j + g];
#pragma unroll
    for (int j = 0; j < 16; ++j) W_reg[32 + j] = C [f * 64 + 4 * j + g];

    int c = blockIdx.x;

    // Prologue: load first chunk's J/X for this thread's (p,d)
    float j0, j1, j2, j3, j4, j5, x0, x1, x2;
    {
        size_t pt = (size_t)c * CHUNK + p;
        const float* Jp = J + (pt * 64 + d) * 6;
        float2 ja = *(const float2*)(Jp + 0);
        float2 jb = *(const float2*)(Jp + 2);
        float2 jc = *(const float2*)(Jp + 4);
        j0 = ja.x; j1 = ja.y; j2 = jb.x; j3 = jb.y; j4 = jc.x; j5 = jc.y;
        const float* Xp = X + (pt * 64 + d) * 3;
        x0 = Xp[0]; x1 = Xp[1]; x2 = Xp[2];
    }

    for (; c < NCHUNKS; c += GRID) {
        // ---------------- Phase A: frames + term construction ----------------
        // a1 = J[...,:,0] = (j0,j2,j4), a2 = J[...,:,1] = (j1,j3,j5)
        float a1x = j0, a1y = j2, a1z = j4;
        float a2x = j1, a2y = j3, a2z = j5;
        float n1 = a1x * a1x + a1y * a1y + a1z * a1z;
        float s1 = rsqrtf(fmaxf(n1, 1e-24f));
        float b1x = a1x * s1, b1y = a1y * s1, b1z = a1z * s1;
        float dt = b1x * a2x + b1y * a2y + b1z * a2z;
        float ux = a2x - dt * b1x, uy = a2y - dt * b1y, uz = a2z - dt * b1z;
        float s2 = rsqrtf(fmaxf(ux * ux + uy * uy + uz * uz, 1e-24f));
        float b2x = ux * s2, b2y = uy * s2, b2z = uz * s2;
        float b3x = b1y * b2z - b1z * b2y;
        float b3y = b1z * b2x - b1x * b2z;
        float b3z = b1x * b2y - b1y * b2x;
        float rt0 = b1x * x0 + b1y * x1 + b1z * x2;
        float rt1 = b2x * x0 + b2y * x1 + b2z * x2;
        float rt2 = b3x * x0 + b3y * x1 + b3z * x2;

        float* Ta = &T_s[(d)       * 12 + p];
        float* Tb = &T_s[(64 + d)  * 12 + p];
        float* Tc = &T_s[(128 + d) * 12 + p];
        Ta[0] = b1x * rt0 + b2x * rt1;  Ta[4] = b1y * rt0 + b2y * rt1;  Ta[8] = b1z * rt0 + b2z * rt1;
        Tb[0] = b2x * rt0 - b1x * rt1;  Tb[4] = b2y * rt0 - b1y * rt1;  Tb[8] = b2z * rt0 - b1z * rt1;
        Tc[0] = b3x * rt2;              Tc[4] = b3y * rt2;              Tc[8] = b3z * rt2;

        __syncthreads();

        // Prefetch next chunk's J/X (latency hidden under the GEMM below)
        int cn = c + GRID;
        if (cn < NCHUNKS) {
            size_t pt = (size_t)cn * CHUNK + p;
            const float* Jp = J + (pt * 64 + d) * 6;
            float2 ja = *(const float2*)(Jp + 0);
            float2 jb = *(const float2*)(Jp + 2);
            float2 jc = *(const float2*)(Jp + 4);
            j0 = ja.x; j1 = ja.y; j2 = jb.x; j3 = jb.y; j4 = jc.x; j5 = jc.y;
            const float* Xp = X + (pt * 64 + d) * 3;
            x0 = Xp[0]; x1 = Xp[1]; x2 = Xp[2];
        }

        // ---------------- Phase B: Y[f, i, p0..p3] = sum_e W[f,e] * T[e,i,p] --
        ull acc00 = 0ull, acc01 = 0ull;   // i=0: points(0,1), (2,3)
        ull acc10 = 0ull, acc11 = 0ull;   // i=1
        ull acc20 = 0ull, acc21 = 0ull;   // i=2
#pragma unroll 8
        for (int j = 0; j < 48; ++j) {
            ull w2 = dup2(W_reg[j]);
            const ulonglong2* t = (const ulonglong2*)&T_s[(4 * j + g) * 12];
            ulonglong2 q0 = t[0];
            ulonglong2 q1 = t[1];
            ulonglong2 q2 = t[2];
            fma2(acc00, w2, q0.x); fma2(acc01, w2, q0.y);
            fma2(acc10, w2, q1.x); fma2(acc11, w2, q1.y);
            fma2(acc20, w2, q2.x); fma2(acc21, w2, q2.y);
        }

        // Reduce across the 4 g-lanes (adjacent lanes in the warp)
        acc00 = add2(acc00, __shfl_xor_sync(0xffffffffu, acc00, 1));
        acc01 = add2(acc01, __shfl_xor_sync(0xffffffffu, acc01, 1));
        acc10 = add2(acc10, __shfl_xor_sync(0xffffffffu, acc10, 1));
        acc11 = add2(acc11, __shfl_xor_sync(0xffffffffu, acc11, 1));
        acc20 = add2(acc20, __shfl_xor_sync(0xffffffffu, acc20, 1));
        acc21 = add2(acc21, __shfl_xor_sync(0xffffffffu, acc21, 1));
        acc00 = add2(acc00, __shfl_xor_sync(0xffffffffu, acc00, 2));
        acc01 = add2(acc01, __shfl_xor_sync(0xffffffffu, acc01, 2));
        acc10 = add2(acc10, __shfl_xor_sync(0xffffffffu, acc10, 2));
        acc11 = add2(acc11, __shfl_xor_sync(0xffffffffu, acc11, 2));
        acc20 = add2(acc20, __shfl_xor_sync(0xffffffffu, acc20, 2));
        acc21 = add2(acc21, __shfl_xor_sync(0xffffffffu, acc21, 2));

        if (g == 0) {
            size_t base = (size_t)c * CHUNK;
            float* Y0 = Y + (base + 0) * 192 + f * 3;
            float* Y1 = Y + (base + 1) * 192 + f * 3;
            float* Y2 = Y + (base + 2) * 192 + f * 3;
            float* Y3 = Y + (base + 3) * 192 + f * 3;
            Y0[0] = lo32(acc00); Y0[1] = lo32(acc10); Y0[2] = lo32(acc20);
            Y1[0] = hi32(acc00); Y1[1] = hi32(acc10); Y1[2] = hi32(acc20);
            Y2[0] = lo32(acc01); Y2[1] = lo32(acc11); Y2[2] = lo32(acc21);
            Y3[0] = hi32(acc01); Y3[1] = hi32(acc11); Y3[2] = hi32(acc21);
        }
        __syncthreads();
    }
}

extern "C" void kernel_launch(void* const* d_in, const int* in_sizes, int n_in,
                              void* d_out, int out_size) {
    // metadata order: X, J, A, Bm, C
    const float* X  = (const float*)d_in[0];
    const float* J  = (const float*)d_in[1];
    const float* A  = (const float*)d_in[2];
    const float* Bm = (const float*)d_in[3];
    const float* C  = (const float*)d_in[4];
    float* Y = (float*)d_out;
    affine_linear_kernel<<<GRID, THREADS>>>(X, J, A, Bm, C, Y);
}

// round 2
// speedup vs baseline: 1.6219x; 1.6219x over previous
#include <cuda_runtime.h>
#include <cstdint>

// Shapes fixed by reference: B=8, N=8192 -> 65536 points, D=64, F=64
#define TOTAL_POINTS 65536
#define CHUNK 4
#define NCHUNKS (TOTAL_POINTS / CHUNK)   // 16384
#define THREADS 256
#define GRID 1024                         // 16 chunks per block exactly

typedef unsigned long long ull;

__device__ __forceinline__ void fma2(ull &acc, ull a, ull b) {
    asm("fma.rn.f32x2 %0, %1, %2, %0;" : "+l"(acc) : "l"(a), "l"(b));
}
__device__ __forceinline__ ull add2(ull a, ull b) {
    ull r; asm("add.rn.f32x2 %0, %1, %2;" : "=l"(r) : "l"(a), "l"(b)); return r;
}
__device__ __forceinline__ ull dup2(float w) {
    ull r; asm("mov.b64 %0, {%1, %1};" : "=l"(r) : "r"(__float_as_uint(w))); return r;
}
__device__ __forceinline__ float lo32(ull v) { return __uint_as_float((unsigned)v); }
__device__ __forceinline__ float hi32(ull v) { return __uint_as_float((unsigned)(v >> 32)); }

__global__ void __launch_bounds__(THREADS, 2)
affine_linear_kernel(const float* __restrict__ X, const float* __restrict__ J,
                     const float* __restrict__ A, const float* __restrict__ Bm,
                     const float* __restrict__ C, float* __restrict__ Y)
{
    // T layout: [e(192)][i(3)][p(4)] floats, e-stride = 12 floats (48B)
    __shared__ float T_s[192 * 12];

    const int tid = threadIdx.x;
    const int f2 = tid >> 3;     // 0..31  (owns output rows 2*f2, 2*f2+1)
    const int g  = tid & 7;      // 0..7   (e partition: e = 8j+g)
    const int p  = tid >> 6;     // 0..3   (point within chunk, phase A)
    const int d  = tid & 63;     // 0..63  (frame index, phase A)

    // W = [A | Bm | C], two rows per thread, columns e = 8j+g (j = 0..23)
    float Wr0[24], Wr1[24];
    {
        const int f0 = 2 * f2, f1 = 2 * f2 + 1;
#pragma unroll
        for (int j = 0; j < 8; ++j) {
            int col = 8 * j + g;
            Wr0[j]      = A [f0 * 64 + col];
            Wr0[8 + j]  = Bm[f0 * 64 + col];
            Wr0[16 + j] = C [f0 * 64 + col];
            Wr1[j]      = A [f1 * 64 + col];
            Wr1[8 + j]  = Bm[f1 * 64 + col];
            Wr1[16 + j] = C [f1 * 64 + col];
        }
    }

    int c = blockIdx.x;

    // Prologue: load first chunk's J/X for this thread's (p,d)
    float j0, j1, j2, j3, j4, j5, x0, x1, x2;
    {
        size_t pt = (size_t)c * CHUNK + p;
        const float* Jp = J + (pt * 64 + d) * 6;
        float2 ja = *(const float2*)(Jp + 0);
        float2 jb = *(const float2*)(Jp + 2);
        float2 jc = *(const float2*)(Jp + 4);
        j0 = ja.x; j1 = ja.y; j2 = jb.x; j3 = jb.y; j4 = jc.x; j5 = jc.y;
        const float* Xp = X + (pt * 64 + d) * 3;
        x0 = Xp[0]; x1 = Xp[1]; x2 = Xp[2];
    }

    for (; c < NCHUNKS; c += GRID) {
        // ---------------- Phase A: frames + term construction ----------------
        float a1x = j0, a1y = j2, a1z = j4;
        float a2x = j1, a2y = j3, a2z = j5;
        float n1 = a1x * a1x + a1y * a1y + a1z * a1z;
        float s1 = rsqrtf(fmaxf(n1, 1e-24f));
        float b1x = a1x * s1, b1y = a1y * s1, b1z = a1z * s1;
        float dt = b1x * a2x + b1y * a2y + b1z * a2z;
        float ux = a2x - dt * b1x, uy = a2y - dt * b1y, uz = a2z - dt * b1z;
        float s2 = rsqrtf(fmaxf(ux * ux + uy * uy + uz * uz, 1e-24f));
        float b2x = ux * s2, b2y = uy * s2, b2z = uz * s2;
        float b3x = b1y * b2z - b1z * b2y;
        float b3y = b1z * b2x - b1x * b2z;
        float b3z = b1x * b2y - b1y * b2x;
        float rt0 = b1x * x0 + b1y * x1 + b1z * x2;
        float rt1 = b2x * x0 + b2y * x1 + b2z * x2;
        float rt2 = b3x * x0 + b3y * x1 + b3z * x2;

        float* Ta = &T_s[(d)       * 12 + p];
        float* Tb = &T_s[(64 + d)  * 12 + p];
        float* Tc = &T_s[(128 + d) * 12 + p];
        Ta[0] = b1x * rt0 + b2x * rt1;  Ta[4] = b1y * rt0 + b2y * rt1;  Ta[8] = b1z * rt0 + b2z * rt1;
        Tb[0] = b2x * rt0 - b1x * rt1;  Tb[4] = b2y * rt0 - b1y * rt1;  Tb[8] = b2z * rt0 - b1z * rt1;
        Tc[0] = b3x * rt2;              Tc[4] = b3y * rt2;              Tc[8] = b3z * rt2;

        __syncthreads();

        // Prefetch next chunk's J/X (latency hidden under the GEMM)
        int cn = c + GRID;
        if (cn < NCHUNKS) {
            size_t pt = (size_t)cn * CHUNK + p;
            const float* Jp = J + (pt * 64 + d) * 6;
            float2 ja = *(const float2*)(Jp + 0);
            float2 jb = *(const float2*)(Jp + 2);
            float2 jc = *(const float2*)(Jp + 4);
            j0 = ja.x; j1 = ja.y; j2 = jb.x; j3 = jb.y; j4 = jc.x; j5 = jc.y;
            const float* Xp = X + (pt * 64 + d) * 3;
            x0 = Xp[0]; x1 = Xp[1]; x2 = Xp[2];
        }

        // -------- Phase B: Y[f, i, p] = sum_e W[f,e] * T[e,i,p], 2 f-rows/thread
        // acc{0,1}[i*2 + pp]: pp=0 packs (p0,p1), pp=1 packs (p2,p3)
        ull acc0[6] = {0, 0, 0, 0, 0, 0};
        ull acc1[6] = {0, 0, 0, 0, 0, 0};
#pragma unroll
        for (int j = 0; j < 24; ++j) {
            const ulonglong2* t = (const ulonglong2*)&T_s[(8 * j + g) * 12];
            ulonglong2 q0 = t[0];
            ulonglong2 q1 = t[1];
            ulonglong2 q2 = t[2];
            ull w0 = dup2(Wr0[j]);
            ull w1 = dup2(Wr1[j]);
            fma2(acc0[0], w0, q0.x); fma2(acc0[1], w0, q0.y);
            fma2(acc0[2], w0, q1.x); fma2(acc0[3], w0, q1.y);
            fma2(acc0[4], w0, q2.x); fma2(acc0[5], w0, q2.y);
            fma2(acc1[0], w1, q0.x); fma2(acc1[1], w1, q0.y);
            fma2(acc1[2], w1, q1.x); fma2(acc1[3], w1, q1.y);
            fma2(acc1[4], w1, q2.x); fma2(acc1[5], w1, q2.y);
        }

        // Reduce across the 8 g-lanes (lane bits 0..2)
#pragma unroll
        for (int m = 1; m <= 4; m <<= 1) {
#pragma unroll
            for (int k = 0; k < 6; ++k) {
                acc0[k] = add2(acc0[k], __shfl_xor_sync(0xffffffffu, acc0[k], m));
                acc1[k] = add2(acc1[k], __shfl_xor_sync(0xffffffffu, acc1[k], m));
            }
        }

        if (g == 0) {
            size_t base = (size_t)c * CHUNK;
            float* Yb = Y + base * 192 + f2 * 6;   // 6 consecutive floats: rows 2f2,2f2+1
            // point 0 (pp=0, lo), point 1 (pp=0, hi), point 2 (pp=1, lo), point 3 (pp=1, hi)
            float2* y0 = (float2*)(Yb + 0 * 192);
            y0[0] = make_float2(lo32(acc0[0]), lo32(acc0[2]));
            y0[1] = make_float2(lo32(acc0[4]), lo32(acc1[0]));
            y0[2] = make_float2(lo32(acc1[2]), lo32(acc1[4]));
            float2* y1 = (float2*)(Yb + 1 * 192);
            y1[0] = make_float2(hi32(acc0[0]), hi32(acc0[2]));
            y1[1] = make_float2(hi32(acc0[4]), hi32(acc1[0]));
            y1[2] = make_float2(hi32(acc1[2]), hi32(acc1[4]));
            float2* y2 = (float2*)(Yb + 2 * 192);
            y2[0] = make_float2(lo32(acc0[1]), lo32(acc0[3]));
            y2[1] = make_float2(lo32(acc0[5]), lo32(acc1[1]));
            y2[2] = make_float2(lo32(acc1[3]), lo32(acc1[5]));
            float2* y3 = (float2*)(Yb + 3 * 192);
            y3[0] = make_float2(hi32(acc0[1]), hi32(acc0[3]));
            y3[1] = make_float2(hi32(acc0[5]), hi32(acc1[1]));
            y3[2] = make_float2(hi32(acc1[3]), hi32(acc1[5]));
        }
        __syncthreads();
    }
}

extern "C" void kernel_launch(void* const* d_in, const int* in_sizes, int n_in,
                              void* d_out, int out_size) {
    // metadata order: X, J, A, Bm, C
    const float* X  = (const float*)d_in[0];
    const float* J  = (const float*)d_in[1];
    const float* A  = (const float*)d_in[2];
    const float* Bm = (const float*)d_in[3];
    const float* C  = (const float*)d_in[4];
    float* Y = (float*)d_out;
    affine_linear_kernel<<<GRID, THREADS>>>(X, J, A, Bm, C, Y);
}

// round 3
// speedup vs baseline: 1.6227x; 1.0005x over previous
#include <cuda_runtime.h>
#include <cstdint>

// Shapes fixed by reference: B=8, N=8192 -> 65536 points, D=64, F=64
#define TOTAL_POINTS 65536
#define CHUNK 4
#define NCHUNKS (TOTAL_POINTS / CHUNK)   // 16384
#define THREADS 256
#define GRID 1024                         // 16 chunks per block exactly

typedef unsigned long long ull;

__device__ __forceinline__ void fma2(ull &acc, ull a, ull b) {
    asm("fma.rn.f32x2 %0, %1, %2, %0;" : "+l"(acc) : "l"(a), "l"(b));
}
__device__ __forceinline__ ull add2(ull a, ull b) {
    ull r; asm("add.rn.f32x2 %0, %1, %2;" : "=l"(r) : "l"(a), "l"(b)); return r;
}
__device__ __forceinline__ ull dup2(float w) {
    ull r; asm("mov.b64 %0, {%1, %1};" : "=l"(r) : "r"(__float_as_uint(w))); return r;
}
__device__ __forceinline__ float lo32(ull v) { return __uint_as_float((unsigned)v); }
__device__ __forceinline__ float hi32(ull v) { return __uint_as_float((unsigned)(v >> 32)); }

__global__ void __launch_bounds__(THREADS, 2)
affine_linear_kernel(const float* __restrict__ X, const float* __restrict__ J,
                     const float* __restrict__ A, const float* __restrict__ Bm,
                     const float* __restrict__ C, float* __restrict__ Y)
{
    // T layout: [e(192)][i(3)][p(4)] floats, e-stride = 12 floats (48B)
    __shared__ float T_s[192 * 12];

    const int tid = threadIdx.x;
    const int f2 = tid >> 3;     // 0..31  (owns output rows 2*f2, 2*f2+1)
    const int g  = tid & 7;      // 0..7   (e partition: e = 8j+g)
    const int p  = tid >> 6;     // 0..3   (point within chunk, phase A)
    const int d  = tid & 63;     // 0..63  (frame index, phase A)

    // W = [A | Bm | C], two rows per thread, columns e = 8j+g (j = 0..23)
    float Wr0[24], Wr1[24];
    {
        const int f0 = 2 * f2, f1 = 2 * f2 + 1;
#pragma unroll
        for (int j = 0; j < 8; ++j) {
            int col = 8 * j + g;
            Wr0[j]      = A [f0 * 64 + col];
            Wr0[8 + j]  = Bm[f0 * 64 + col];
            Wr0[16 + j] = C [f0 * 64 + col];
            Wr1[j]      = A [f1 * 64 + col];
            Wr1[8 + j]  = Bm[f1 * 64 + col];
            Wr1[16 + j] = C [f1 * 64 + col];
        }
    }

    int c = blockIdx.x;

    // Prologue: load first chunk's J/X for this thread's (p,d)
    float j0, j1, j2, j3, j4, j5, x0, x1, x2;
    {
        size_t pt = (size_t)c * CHUNK + p;
        const float* Jp = J + (pt * 64 + d) * 6;
        float2 ja = *(const float2*)(Jp + 0);
        float2 jb = *(const float2*)(Jp + 2);
        float2 jc = *(const float2*)(Jp + 4);
        j0 = ja.x; j1 = ja.y; j2 = jb.x; j3 = jb.y; j4 = jc.x; j5 = jc.y;
        const float* Xp = X + (pt * 64 + d) * 3;
        x0 = Xp[0]; x1 = Xp[1]; x2 = Xp[2];
    }

    for (; c < NCHUNKS; c += GRID) {
        // ---------------- Phase A: frames + term construction ----------------
        float a1x = j0, a1y = j2, a1z = j4;
        float a2x = j1, a2y = j3, a2z = j5;
        float n1 = a1x * a1x + a1y * a1y + a1z * a1z;
        float s1 = rsqrtf(fmaxf(n1, 1e-24f));
        float b1x = a1x * s1, b1y = a1y * s1, b1z = a1z * s1;
        float dt = b1x * a2x + b1y * a2y + b1z * a2z;
        float ux = a2x - dt * b1x, uy = a2y - dt * b1y, uz = a2z - dt * b1z;
        float s2 = rsqrtf(fmaxf(ux * ux + uy * uy + uz * uz, 1e-24f));
        float b2x = ux * s2, b2y = uy * s2, b2z = uz * s2;
        float b3x = b1y * b2z - b1z * b2y;
        float b3y = b1z * b2x - b1x * b2z;
        float b3z = b1x * b2y - b1y * b2x;
        float rt0 = b1x * x0 + b1y * x1 + b1z * x2;
        float rt1 = b2x * x0 + b2y * x1 + b2z * x2;
        float rt2 = b3x * x0 + b3y * x1 + b3z * x2;

        float* Ta = &T_s[(d)       * 12 + p];
        float* Tb = &T_s[(64 + d)  * 12 + p];
        float* Tc = &T_s[(128 + d) * 12 + p];
        Ta[0] = b1x * rt0 + b2x * rt1;  Ta[4] = b1y * rt0 + b2y * rt1;  Ta[8] = b1z * rt0 + b2z * rt1;
        Tb[0] = b2x * rt0 - b1x * rt1;  Tb[4] = b2y * rt0 - b1y * rt1;  Tb[8] = b2z * rt0 - b1z * rt1;
        Tc[0] = b3x * rt2;              Tc[4] = b3y * rt2;              Tc[8] = b3z * rt2;

        __syncthreads();

        // Prefetch next chunk's J/X (latency hidden under the GEMM)
        int cn = c + GRID;
        if (cn < NCHUNKS) {
            size_t pt = (size_t)cn * CHUNK + p;
            const float* Jp = J + (pt * 64 + d) * 6;
            float2 ja = *(const float2*)(Jp + 0);
            float2 jb = *(const float2*)(Jp + 2);
            float2 jc = *(const float2*)(Jp + 4);
            j0 = ja.x; j1 = ja.y; j2 = jb.x; j3 = jb.y; j4 = jc.x; j5 = jc.y;
            const float* Xp = X + (pt * 64 + d) * 3;
            x0 = Xp[0]; x1 = Xp[1]; x2 = Xp[2];
        }

        // -------- Phase B: Y[f, i, p] = sum_e W[f,e] * T[e,i,p], 2 f-rows/thread
        // acc{0,1}[i*2 + pp]: pp=0 packs (p0,p1), pp=1 packs (p2,p3)
        ull acc0[6] = {0, 0, 0, 0, 0, 0};
        ull acc1[6] = {0, 0, 0, 0, 0, 0};
#pragma unroll
        for (int j = 0; j < 24; ++j) {
            const ulonglong2* t = (const ulonglong2*)&T_s[(8 * j + g) * 12];
            ulonglong2 q0 = t[0];
            ulonglong2 q1 = t[1];
            ulonglong2 q2 = t[2];
            ull w0 = dup2(Wr0[j]);
            ull w1 = dup2(Wr1[j]);
            fma2(acc0[0], w0, q0.x); fma2(acc0[1], w0, q0.y);
            fma2(acc0[2], w0, q1.x); fma2(acc0[3], w0, q1.y);
            fma2(acc0[4], w0, q2.x); fma2(acc0[5], w0, q2.y);
            fma2(acc1[0], w1, q0.x); fma2(acc1[1], w1, q0.y);
            fma2(acc1[2], w1, q1.x); fma2(acc1[3], w1, q1.y);
            fma2(acc1[4], w1, q2.x); fma2(acc1[5], w1, q2.y);
        }

        // Reduce across the 8 g-lanes (lane bits 0..2)
#pragma unroll
        for (int m = 1; m <= 4; m <<= 1) {
#pragma unroll
            for (int k = 0; k < 6; ++k) {
                acc0[k] = add2(acc0[k], __shfl_xor_sync(0xffffffffu, acc0[k], m));
                acc1[k] = add2(acc1[k], __shfl_xor_sync(0xffffffffu, acc1[k], m));
            }
        }

        if (g == 0) {
            size_t base = (size_t)c * CHUNK;
            float* Yb = Y + base * 192 + f2 * 6;   // 6 consecutive floats: rows 2f2,2f2+1
            // point 0 (pp=0, lo), point 1 (pp=0, hi), point 2 (pp=1, lo), point 3 (pp=1, hi)
            float2* y0 = (float2*)(Yb + 0 * 192);
            y0[0] = make_float2(lo32(acc0[0]), lo32(acc0[2]));
            y0[1] = make_float2(lo32(acc0[4]), lo32(acc1[0]));
            y0[2] = make_float2(lo32(acc1[2]), lo32(acc1[4]));
            float2* y1 = (float2*)(Yb + 1 * 192);
            y1[0] = make_float2(hi32(acc0[0]), hi32(acc0[2]));
            y1[1] = make_float2(hi32(acc0[4]), hi32(acc1[0]));
            y1[2] = make_float2(hi32(acc1[2]), hi32(acc1[4]));
            float2* y2 = (float2*)(Yb + 2 * 192);
            y2[0] = make_float2(lo32(acc0[1]), lo32(acc0[3]));
            y2[1] = make_float2(lo32(acc0[5]), lo32(acc1[1]));
            y2[2] = make_float2(lo32(acc1[3]), lo32(acc1[5]));
            float2* y3 = (float2*)(Yb + 3 * 192);
            y3[0] = make_float2(hi32(acc0[1]), hi32(acc0[3]));
            y3[1] = make_float2(hi32(acc0[5]), hi32(acc1[1]));
            y3[2] = make_float2(hi32(acc1[3]), hi32(acc1[5]));
        }
        __syncthreads();
    }
}

extern "C" void kernel_launch(void* const* d_in, const int* in_sizes, int n_in,
                              void* d_out, int out_size) {
    // metadata order: X, J, A, Bm, C
    const float* X  = (const float*)d_in[0];
    const float* J  = (const float*)d_in[1];
    const float* A  = (const float*)d_in[2];
    const float* Bm = (const float*)d_in[3];
    const float* C  = (const float*)d_in[4];
    float* Y = (float*)d_out;
    affine_linear_kernel<<<GRID, THREADS>>>(X, J, A, Bm, C, Y);
}

// round 4
// speedup vs baseline: 1.9962x; 1.2302x over previous
#include <cuda_runtime.h>
#include <cstdint>

// Shapes fixed by reference: B=8, N=8192 -> 65536 points, D=64, F=64
#define TOTAL_POINTS 65536
#define NCHUNKS (TOTAL_POINTS / 2)   // CHUNK = 2 points
#define THREADS 256
#define GRID 2048                     // 32768/2048 = 16 chunks per block exactly

typedef unsigned long long ull;

__device__ __forceinline__ void fma2(ull &acc, ull a, ull b) {
    asm("fma.rn.f32x2 %0, %1, %2, %0;" : "+l"(acc) : "l"(a), "l"(b));
}
__device__ __forceinline__ ull add2(ull a, ull b) {
    ull r; asm("add.rn.f32x2 %0, %1, %2;" : "=l"(r) : "l"(a), "l"(b)); return r;
}
__device__ __forceinline__ ull dup2(float w) {
    ull r; asm("mov.b64 %0, {%1, %1};" : "=l"(r) : "r"(__float_as_uint(w))); return r;
}
__device__ __forceinline__ float lo32(ull v) { return __uint_as_float((unsigned)v); }
__device__ __forceinline__ float hi32(ull v) { return __uint_as_float((unsigned)(v >> 32)); }

__global__ void __launch_bounds__(THREADS, 2)
affine_linear_kernel(const float* __restrict__ X, const float* __restrict__ J,
                     const float* __restrict__ A, const float* __restrict__ Bm,
                     const float* __restrict__ C, float* __restrict__ Y)
{
    // T layout: [e(192)][i(3)][p(2)] floats; index = e*6 + i*2 + p
    __shared__ float T_s[192 * 6];

    const int tid = threadIdx.x;
    const int w = tid >> 5;     // warp 0..7 owns output rows 8w..8w+7
    const int g = tid & 31;     // e-partition lane: e = 32j + g

    // W = [A | Bm | C] : 8 rows x 6 e-columns per thread, in registers (48 floats)
    // j=0: A[.,g]  j=1: A[.,32+g]  j=2: Bm[.,g]  j=3: Bm[.,32+g]  j=4: C[.,g]  j=5: C[.,32+g]
    float Wf[48];
#pragma unroll
    for (int r = 0; r < 8; ++r) {
        const int f = 8 * w + r;
        Wf[r * 6 + 0] = A [f * 64 + g];
        Wf[r * 6 + 1] = A [f * 64 + 32 + g];
        Wf[r * 6 + 2] = Bm[f * 64 + g];
        Wf[r * 6 + 3] = Bm[f * 64 + 32 + g];
        Wf[r * 6 + 4] = C [f * 64 + g];
        Wf[r * 6 + 5] = C [f * 64 + 32 + g];
    }

    // Phase A mapping (threads 0..127 only): d = frame idx, p = point in chunk
    const int d = (tid & 127) >> 1;
    const int p = tid & 1;
    const bool phaseA = tid < 128;

    int c = blockIdx.x;

    // Prologue: load first chunk's J/X
    float j0, j1, j2, j3, j4, j5, x0, x1, x2;
    if (phaseA) {
        size_t pt = (size_t)c * 2 + p;
        const float* Jp = J + (pt * 64 + d) * 6;
        float2 ja = *(const float2*)(Jp + 0);
        float2 jb = *(const float2*)(Jp + 2);
        float2 jc = *(const float2*)(Jp + 4);
        j0 = ja.x; j1 = ja.y; j2 = jb.x; j3 = jb.y; j4 = jc.x; j5 = jc.y;
        const float* Xp = X + (pt * 64 + d) * 3;
        x0 = Xp[0]; x1 = Xp[1]; x2 = Xp[2];
    }

    for (; c < NCHUNKS; c += GRID) {
        // ---------------- Phase A: frames + term construction ----------------
        if (phaseA) {
            float a1x = j0, a1y = j2, a1z = j4;
            float a2x = j1, a2y = j3, a2z = j5;
            float n1 = a1x * a1x + a1y * a1y + a1z * a1z;
            float s1 = rsqrtf(fmaxf(n1, 1e-24f));
            float b1x = a1x * s1, b1y = a1y * s1, b1z = a1z * s1;
            float dt = b1x * a2x + b1y * a2y + b1z * a2z;
            float ux = a2x - dt * b1x, uy = a2y - dt * b1y, uz = a2z - dt * b1z;
            float s2 = rsqrtf(fmaxf(ux * ux + uy * uy + uz * uz, 1e-24f));
            float b2x = ux * s2, b2y = uy * s2, b2z = uz * s2;
            float b3x = b1y * b2z - b1z * b2y;
            float b3y = b1z * b2x - b1x * b2z;
            float b3z = b1x * b2y - b1y * b2x;
            float rt0 = b1x * x0 + b1y * x1 + b1z * x2;
            float rt1 = b2x * x0 + b2y * x1 + b2z * x2;
            float rt2 = b3x * x0 + b3y * x1 + b3z * x2;

            // STS (conflict-free: bank = (6d + 2i + p) mod 32, all distinct per warp)
            float* Ta = &T_s[(d)       * 6 + p];
            float* Tb = &T_s[(64 + d)  * 6 + p];
            float* Tc = &T_s[(128 + d) * 6 + p];
            Ta[0] = b1x * rt0 + b2x * rt1;  Ta[2] = b1y * rt0 + b2y * rt1;  Ta[4] = b1z * rt0 + b2z * rt1;
            Tb[0] = b2x * rt0 - b1x * rt1;  Tb[2] = b2y * rt0 - b1y * rt1;  Tb[4] = b2z * rt0 - b1z * rt1;
            Tc[0] = b3x * rt2;              Tc[2] = b3y * rt2;              Tc[4] = b3z * rt2;
        }
        __syncthreads();

        // Prefetch next chunk's J/X (hidden under the GEMM)
        int cn = c + GRID;
        if (phaseA && cn < NCHUNKS) {
            size_t pt = (size_t)cn * 2 + p;
            const float* Jp = J + (pt * 64 + d) * 6;
            float2 ja = *(const float2*)(Jp + 0);
            float2 jb = *(const float2*)(Jp + 2);
            float2 jc = *(const float2*)(Jp + 4);
            j0 = ja.x; j1 = ja.y; j2 = jb.x; j3 = jb.y; j4 = jc.x; j5 = jc.y;
            const float* Xp = X + (pt * 64 + d) * 3;
            x0 = Xp[0]; x1 = Xp[1]; x2 = Xp[2];
        }

        // ------- Phase B: 8 rows/thread, e = 32j + g, acc packs (p0,p1) -------
        ull acc[24];
#pragma unroll
        for (int k = 0; k < 24; ++k) acc[k] = 0ull;
#pragma unroll
        for (int j = 0; j < 6; ++j) {
            const float* tp = &T_s[(32 * j + g) * 6];
            ull t0 = *(const ull*)(tp + 0);
            ull t1 = *(const ull*)(tp + 2);
            ull t2 = *(const ull*)(tp + 4);
#pragma unroll
            for (int r = 0; r < 8; ++r) {
                ull wv = dup2(Wf[r * 6 + j]);
                fma2(acc[r * 3 + 0], wv, t0);
                fma2(acc[r * 3 + 1], wv, t1);
                fma2(acc[r * 3 + 2], wv, t2);
            }
        }

        // ---- Collapsing reduction over 32 e-lanes ----
        // Round 1 (xor 16): rows 8 -> 4
        {
            const bool b = (g & 16) != 0;
#pragma unroll
            for (int k = 0; k < 12; ++k) {
                ull give = b ? acc[k] : acc[k + 12];
                ull got  = __shfl_xor_sync(0xffffffffu, give, 16);
                ull keep = b ? acc[k + 12] : acc[k];
                acc[k] = add2(keep, got);
            }
        }
        // Round 2 (xor 8): rows 4 -> 2
        {
            const bool b = (g & 8) != 0;
#pragma unroll
            for (int k = 0; k < 6; ++k) {
                ull give = b ? acc[k] : acc[k + 6];
                ull got  = __shfl_xor_sync(0xffffffffu, give, 8);
                ull keep = b ? acc[k + 6] : acc[k];
                acc[k] = add2(keep, got);
            }
        }
        // Round 3 (xor 4): rows 2 -> 1
        {
            const bool b = (g & 4) != 0;
#pragma unroll
            for (int k = 0; k < 3; ++k) {
                ull give = b ? acc[k] : acc[k + 3];
                ull got  = __shfl_xor_sync(0xffffffffu, give, 4);
                ull keep = b ? acc[k + 3] : acc[k];
                acc[k] = add2(keep, got);
            }
        }
        // Rounds 4,5 (xor 2, xor 1): plain
#pragma unroll
        for (int k = 0; k < 3; ++k)
            acc[k] = add2(acc[k], __shfl_xor_sync(0xffffffffu, acc[k], 2));
#pragma unroll
        for (int k = 0; k < 3; ++k)
            acc[k] = add2(acc[k], __shfl_xor_sync(0xffffffffu, acc[k], 1));

        // Store: lanes g = 0,4,...,28 hold row r_local = bits{g4,g3,g2}
        if ((g & 3) == 0) {
            const int r_local = ((g >> 4) & 1) * 4 + ((g >> 3) & 1) * 2 + ((g >> 2) & 1);
            const int f = 8 * w + r_local;
            size_t base0 = (size_t)c * 2 * 192 + f * 3;
            Y[base0 + 0]   = lo32(acc[0]);
            Y[base0 + 1]   = lo32(acc[1]);
            Y[base0 + 2]   = lo32(acc[2]);
            Y[base0 + 192] = hi32(acc[0]);
            Y[base0 + 193] = hi32(acc[1]);
            Y[base0 + 194] = hi32(acc[2]);
        }
        __syncthreads();
    }
}

extern "C" void kernel_launch(void* const* d_in, const int* in_sizes, int n_in,
                              void* d_out, int out_size) {
    // metadata order: X, J, A, Bm, C
    const float* X  = (const float*)d_in[0];
    const float* J  = (const float*)d_in[1];
    const float* A  = (const float*)d_in[2];
    const float* Bm = (const float*)d_in[3];
    const float* C  = (const float*)d_in[4];
    float* Y = (float*)d_out;
    affine_linear_kernel<<<GRID, THREADS>>>(X, J, A, Bm, C, Y);
}